// round 8
// baseline (speedup 1.0000x reference)
#include <cuda_runtime.h>

#define MAXN 100000
#define MAXE 1600000
#define NEG 0.2f

typedef unsigned long long ull;

// ---------------- scratch (static device globals; no allocation) -------------
__device__ float g_h0 [MAXN * 16];    // relu(x@W0)
__device__ float g_hl [MAXN * 96];    // source transform (current layer)
__device__ float g_hr [MAXN * 96];    // target transform (current layer)
__device__ float g_acc[MAXN * 96];    // layer-1 accumulator = skip + b1 + msgs
__device__ float g_wt [3 * 96 * 96];  // layer-2 weights transposed [mat][c][k]
__device__ int   g_src[MAXE];
__device__ int   g_dst[MAXE];
__device__ int   g_ssrc[MAXE];        // src ids sorted by dst (CSR payload)
__device__ int   g_cnt[MAXN];         // in-degree histogram
__device__ int   g_rs [MAXN + 1];     // CSR row starts
__device__ int   g_cur[MAXN];         // scatter cursors
__device__ int   g_bsum[128];
__device__ int   g_boff[128];
__device__ int   g_is64;

// ---------------- asm helpers -------------------------------------------------
__device__ __forceinline__ void ffma2(ull& acc, ull a, ull b) {
    asm("fma.rn.f32x2 %0, %1, %2, %0;" : "+l"(acc) : "l"(a), "l"(b));
}
__device__ __forceinline__ ull pack2(float x, float y) {
    ull r; asm("mov.b64 %0, {%1, %2};" : "=l"(r) : "f"(x), "f"(y)); return r;
}
__device__ __forceinline__ float2 unpack2(ull v) {
    float2 r; asm("mov.b64 {%0, %1}, %2;" : "=f"(r.x), "=f"(r.y) : "l"(v)); return r;
}
// integer warp-wide sum w/ broadcast (sm_80+; f32 redux does NOT exist on sm_103)
__device__ __forceinline__ int warp_sum_i(int v) {
    int r;
    asm("redux.sync.add.s32 %0, %1, 0xffffffff;" : "=r"(r) : "r"(v));
    return r;
}
__device__ __forceinline__ float ex2(float v) {
    float r; asm("ex2.approx.ftz.f32 %0, %1;" : "=f"(r) : "f"(v)); return r;
}

#define FPSCALE 262144.0f            /* 2^18 fixed-point score scale */
#define INV_FPSCALE 3.814697265625e-06f

// ---------------- init: zero histogram + dtype detect -------------------------
// Detect int64 vs int32 edge_index: node ids < 2^17, so int64 => odd words 0.
__global__ void k_init(const int* __restrict__ p, int n) {
    int i = blockIdx.x * blockDim.x + threadIdx.x;
    if (i < n) g_cnt[i] = 0;
    if (i == 0) {
        int acc = 0;
#pragma unroll
        for (int j = 1; j < 64; j += 2) acc |= p[j];
        g_is64 = (acc == 0) ? 1 : 0;
    }
}

// transpose layer-2 weights: g_wt[m*9216 + c*96 + k] = W[k*96 + c]
__global__ void k_wt(const float* __restrict__ Wl, const float* __restrict__ Wr,
                     const float* __restrict__ Wo) {
    int i = blockIdx.x * blockDim.x + threadIdx.x;
    if (i >= 9216) return;
    int c = i / 96, k = i % 96;
    float a = Wl[k * 96 + c], b = Wr[k * 96 + c], d = Wo[k * 96 + c];
    g_wt[i] = a;
    g_wt[9216 + i] = b;
    g_wt[2 * 9216 + i] = d;
}

__global__ void k_edges(const void* __restrict__ ei, int E) {
    int i = blockIdx.x * blockDim.x + threadIdx.x;
    if (i >= E) return;
    int s, d;
    if (g_is64) {
        const long long* p = (const long long*)ei;
        s = (int)p[i]; d = (int)p[E + i];
    } else {
        const int* p = (const int*)ei;
        s = p[i]; d = p[E + i];
    }
    g_src[i] = s;
    g_dst[i] = d;
    atomicAdd(&g_cnt[d], 1);
}

// ---------------- scan (3-kernel exclusive prefix sum over g_cnt) ------------

__global__ void k_scan1(int n) {
    __shared__ int tmp[1024];
    int tid = threadIdx.x;
    int i = blockIdx.x * 1024 + tid;
    int v = (i < n) ? g_cnt[i] : 0;
    tmp[tid] = v;
    __syncthreads();
#pragma unroll
    for (int o = 1; o < 1024; o <<= 1) {
        int t = (tid >= o) ? tmp[tid - o] : 0;
        __syncthreads();
        tmp[tid] += t;
        __syncthreads();
    }
    if (i < n) g_rs[i] = tmp[tid] - v;         // block-local exclusive
    if (tid == 1023) g_bsum[blockIdx.x] = tmp[tid];
}

__global__ void k_scan2(int nb) {
    __shared__ int tmp[128];
    int tid = threadIdx.x;
    int v = (tid < nb) ? g_bsum[tid] : 0;
    tmp[tid] = v;
    __syncthreads();
#pragma unroll
    for (int o = 1; o < 128; o <<= 1) {
        int t = (tid >= o) ? tmp[tid - o] : 0;
        __syncthreads();
        tmp[tid] += t;
        __syncthreads();
    }
    if (tid < nb) g_boff[tid] = tmp[tid] - v;  // exclusive block offsets
}

__global__ void k_scan3(int n, int E) {
    int i = blockIdx.x * blockDim.x + threadIdx.x;
    if (i < n) {
        int r = g_rs[i] + g_boff[i >> 10];
        g_rs[i] = r;
        g_cur[i] = r;
    }
    if (i == 0) g_rs[n] = E;
}

__global__ void k_scatter(int E) {
    int i = blockIdx.x * blockDim.x + threadIdx.x;
    if (i >= E) return;
    int d = g_dst[i];
    int pos = atomicAdd(&g_cur[d], 1);
    g_ssrc[pos] = g_src[i];
}

// ---------------- node transforms --------------------------------------------

// h0 = relu(x @ W0) : [n,128]@[128,16]. Shared-staged, float4 global loads.
__global__ void __launch_bounds__(256)
k_lin0(const float* __restrict__ x, const float* __restrict__ W0, int n) {
    __shared__ float sx[16 * 128];   // 16 rows of x
    __shared__ float sw[128 * 16];   // W0
    int tid = threadIdx.x;
    int row0 = blockIdx.x * 16;
    for (int i = tid; i < 512; i += 256)
        ((float4*)sw)[i] = ((const float4*)W0)[i];
    for (int i = tid; i < 512; i += 256) {
        int r = i >> 5;                // row within tile
        int row = row0 + r;
        float4 v = make_float4(0.f, 0.f, 0.f, 0.f);
        if (row < n) v = ((const float4*)x)[row * 32 + (i & 31)];
        ((float4*)sx)[i] = v;
    }
    __syncthreads();
    int r = tid >> 4, c = tid & 15;
    const float4* sxr = (const float4*)(sx + r * 128);
    float acc = 0.f;
#pragma unroll
    for (int k4 = 0; k4 < 32; k4++) {
        float4 h = sxr[k4];
        acc = fmaf(h.x, sw[(4 * k4 + 0) * 16 + c], acc);
        acc = fmaf(h.y, sw[(4 * k4 + 1) * 16 + c], acc);
        acc = fmaf(h.z, sw[(4 * k4 + 2) * 16 + c], acc);
        acc = fmaf(h.w, sw[(4 * k4 + 3) * 16 + c], acc);
    }
    int row = row0 + r;
    if (row < n) g_h0[row * 16 + c] = fmaxf(acc, 0.f);
}

// layer-1 transforms: weights in registers (one output column per thread),
// h rows staged in shared (broadcast reads). 64 rows per block.
__global__ void __launch_bounds__(384)
k_node1(const float* __restrict__ Wl, const float* __restrict__ bl,
        const float* __restrict__ Wr, const float* __restrict__ br,
        const float* __restrict__ Wf, const float* __restrict__ bf,
        const float* __restrict__ b1, int n) {
    __shared__ float sh[64 * 16];
    int c = threadIdx.x, ty = threadIdx.y;
    int tid = ty * 96 + c;
    int row0 = blockIdx.x * 64;
    float wl[16], wr[16], wf[16];
#pragma unroll
    for (int k = 0; k < 16; k++) {
        wl[k] = Wl[k * 96 + c];
        wr[k] = Wr[k * 96 + c];
        wf[k] = Wf[k * 96 + c];
    }
    float cbl = bl[c], cbr = br[c], cbf = bf[c] + b1[c];
    for (int i = tid; i < 1024; i += 384) {
        int r = i >> 4, k = i & 15;
        int row = row0 + r;
        sh[i] = (row < n) ? g_h0[row * 16 + k] : 0.f;
    }
    __syncthreads();
    for (int r = ty; r < 64; r += 4) {
        int row = row0 + r;
        if (row >= n) continue;
        float a0 = cbl, a1 = cbr, a2 = cbf;
#pragma unroll
        for (int k = 0; k < 16; k++) {
            float h = sh[r * 16 + k];
            a0 = fmaf(h, wl[k], a0);
            a1 = fmaf(h, wr[k], a1);
            a2 = fmaf(h, wf[k], a2);
        }
        g_hl[row * 96 + c] = a0;
        g_hr[row * 96 + c] = a1;
        g_acc[row * 96 + c] = a2;
    }
}

// layer-2 transforms via packed f32x2 FMA (FFMA2), weights from the
// TRANSPOSED copy g_wt so each chunk's 48 weights come in as 12 LDG.128
// (stride-96 scalar weight LDG made the old version LSU-bound).
// sh is transposed [k][r] stride 34 (aligned LDS.64, conflict-free).
__global__ void __launch_bounds__(384, 1)
k_node2(const float* __restrict__ bl, const float* __restrict__ br,
        const float* __restrict__ bo, const float* __restrict__ b2,
        float* __restrict__ out, int n) {
    __shared__ float sh[16 * 34];
    int c = threadIdx.x, ty = threadIdx.y;
    int tid = ty * 96 + c;
    int row0 = blockIdx.x * 32;
    ull a0[4], a1[4], a2[4];
    float ibl = bl[c], ibr = br[c], ibo = bo[c] + b2[c];
#pragma unroll
    for (int jp = 0; jp < 4; jp++) {
        a0[jp] = pack2(ibl, ibl);
        a1[jp] = pack2(ibr, ibr);
        a2[jp] = pack2(ibo, ibo);
    }
    for (int kt = 0; kt < 6; kt++) {
        float wl[16], wr[16], wo[16];
        {
            const float4* pl = (const float4*)(g_wt + c * 96 + kt * 16);
            const float4* pr = (const float4*)(g_wt + 9216 + c * 96 + kt * 16);
            const float4* po = (const float4*)(g_wt + 2 * 9216 + c * 96 + kt * 16);
#pragma unroll
            for (int q = 0; q < 4; q++) {
                float4 v = pl[q];
                wl[4 * q] = v.x; wl[4 * q + 1] = v.y; wl[4 * q + 2] = v.z; wl[4 * q + 3] = v.w;
                v = pr[q];
                wr[4 * q] = v.x; wr[4 * q + 1] = v.y; wr[4 * q + 2] = v.z; wr[4 * q + 3] = v.w;
                v = po[q];
                wo[4 * q] = v.x; wo[4 * q + 1] = v.y; wo[4 * q + 2] = v.z; wo[4 * q + 3] = v.w;
            }
        }
        for (int i = tid; i < 512; i += 384) {
            int k = i & 15, r = i >> 4;
            int row = row0 + r;
            float v = (row < n) ? g_acc[row * 96 + kt * 16 + k] : 0.f;
            sh[k * 34 + r] = fmaxf(v, 0.f);   // relu(h1), transposed
        }
        __syncthreads();
#pragma unroll
        for (int k = 0; k < 16; k++) {
            ull wl2 = pack2(wl[k], wl[k]);
            ull wr2 = pack2(wr[k], wr[k]);
            ull wo2 = pack2(wo[k], wo[k]);
#pragma unroll
            for (int jp = 0; jp < 4; jp++) {
                int p = ty + 4 * jp;
                ull h2 = *(const ull*)&sh[k * 34 + 2 * p];
                ffma2(a0[jp], h2, wl2);
                ffma2(a1[jp], h2, wr2);
                ffma2(a2[jp], h2, wo2);
            }
        }
        __syncthreads();
    }
#pragma unroll
    for (int jp = 0; jp < 4; jp++) {
        int p = ty + 4 * jp;
        float2 v0 = unpack2(a0[jp]);
        float2 v1 = unpack2(a1[jp]);
        float2 v2 = unpack2(a2[jp]);
        int ra = row0 + 2 * p, rb = ra + 1;
        if (ra < n) {
            g_hl[ra * 96 + c] = v0.x; g_hr[ra * 96 + c] = v1.x; out[ra * 96 + c] = v2.x;
        }
        if (rb < n) {
            g_hl[rb * 96 + c] = v0.y; g_hr[rb * 96 + c] = v1.y; out[rb * 96 + c] = v2.y;
        }
    }
}

// ---------------- fused GATv2 edge phase (warp per destination node) ---------
// lane l covers channels l (head0), 32+l (head1), 64+l (head2).
// Warp dot-products via FIXED-POINT redux.sync.add.s32 (f32 redux absent on
// sm_103): att pre-scaled by log2(e)*2^18; per-lane partial rounded to int,
// warp-summed in 1 instr, converted back, ex2. Error ~1e-5 << 1e-3 gate.
// NOTE: internal target (g_acc) resolved in DEVICE code (host symbol != dev ptr).
__global__ void k_gat(const float* __restrict__ att, float* __restrict__ ext_out,
                      int use_internal, int n) {
    int v = (blockIdx.x * blockDim.x + threadIdx.x) >> 5;
    int lane = threadIdx.x & 31;
    if (v >= n) return;
    float* out = use_internal ? g_acc : ext_out;
    int beg = g_rs[v], end = g_rs[v + 1];
    const float SC = 1.44269504088896340736f * FPSCALE;
    float at0 = att[lane] * SC, at1 = att[32 + lane] * SC, at2 = att[64 + lane] * SC;
    const float* hr = g_hr + (size_t)v * 96;
    float hr0 = hr[lane], hr1 = hr[32 + lane], hr2 = hr[64 + lane];
    float den0 = 0.f, den1 = 0.f, den2 = 0.f;
    float ac0 = 0.f, ac1 = 0.f, ac2 = 0.f;
    for (int base = beg; base < end; base += 32) {
        int m = end - base; if (m > 32) m = 32;
        int myi = (lane < m) ? g_ssrc[base + lane] : 0;
#pragma unroll 4
        for (int j = 0; j < m; j++) {
            int s = __shfl_sync(0xffffffffu, myi, j);
            const float* hl = g_hl + (size_t)s * 96;
            float h0 = hl[lane], h1 = hl[32 + lane], h2 = hl[64 + lane];
            float v0 = h0 + hr0, v1 = h1 + hr1, v2 = h2 + hr2;
            v0 = fmaxf(v0, NEG * v0);           // leaky relu (0<NEG<1)
            v1 = fmaxf(v1, NEG * v1);
            v2 = fmaxf(v2, NEG * v2);
            int i0 = warp_sum_i(__float2int_rn(at0 * v0));
            int i1 = warp_sum_i(__float2int_rn(at1 * v1));
            int i2 = warp_sum_i(__float2int_rn(at2 * v2));
            float p0 = ex2((float)i0 * INV_FPSCALE);
            float p1 = ex2((float)i1 * INV_FPSCALE);
            float p2 = ex2((float)i2 * INV_FPSCALE);
            den0 += p0; den1 += p1; den2 += p2;
            ac0 = fmaf(p0, h0, ac0);
            ac1 = fmaf(p1, h1, ac1);
            ac2 = fmaf(p2, h2, ac2);
        }
    }
    float* o = out + (size_t)v * 96;
    o[lane]      += __fdividef(ac0, den0 + 1e-16f);
    o[32 + lane] += __fdividef(ac1, den1 + 1e-16f);
    o[64 + lane] += __fdividef(ac2, den2 + 1e-16f);
}

// ---------------- launch ------------------------------------------------------

extern "C" void kernel_launch(void* const* d_in, const int* in_sizes, int n_in,
                              void* d_out, int out_size) {
    const float* x     = (const float*)d_in[0];
    const void*  ei    = (const void*)d_in[1];
    const float* W0    = (const float*)d_in[2];
    const float* Wl1   = (const float*)d_in[3];
    const float* bl1   = (const float*)d_in[4];
    const float* Wr1   = (const float*)d_in[5];
    const float* br1   = (const float*)d_in[6];
    const float* att1  = (const float*)d_in[7];
    const float* b1    = (const float*)d_in[8];
    const float* Wf    = (const float*)d_in[9];
    const float* bf    = (const float*)d_in[10];
    const float* Wl2   = (const float*)d_in[11];
    const float* bl2   = (const float*)d_in[12];
    const float* Wr2   = (const float*)d_in[13];
    const float* br2   = (const float*)d_in[14];
    const float* att2  = (const float*)d_in[15];
    const float* b2    = (const float*)d_in[16];
    const float* Wlast = (const float*)d_in[17];
    const float* blast = (const float*)d_in[18];
    float* out = (float*)d_out;

    int n = in_sizes[0] / 128;
    int E = in_sizes[1] / 2;
    int NB = (n + 1023) / 1024;          // scan blocks (<=128)

    // ---- CSR build (by destination) + weight transpose ----
    k_init<<<(n + 255) / 256, 256>>>((const int*)ei, n);
    k_wt<<<(9216 + 255) / 256, 256>>>(Wl2, Wr2, Wlast);
    k_edges<<<(E + 255) / 256, 256>>>(ei, E);
    k_scan1<<<NB, 1024>>>(n);
    k_scan2<<<1, 128>>>(NB);
    k_scan3<<<(n + 255) / 256, 256>>>(n, E);
    k_scatter<<<(E + 255) / 256, 256>>>(E);

    // ---- node transforms ----
    k_lin0<<<(n + 15) / 16, 256>>>(x, W0, n);
    k_node1<<<(n + 63) / 64, dim3(96, 4)>>>(Wl1, bl1, Wr1, br1, Wf, bf, b1, n);

    // ---- layer 1 edge phase (into g_acc which holds skip + b1) ----
    k_gat<<<(n + 7) / 8, 256>>>(att1, out, 1, n);

    // ---- layer 2 node transforms (relu fused on load; out gets skip + b2) ----
    k_node2<<<(n + 31) / 32, dim3(96, 4)>>>(bl2, br2, blast, b2, out, n);

    // ---- layer 2 edge phase (into d_out) ----
    k_gat<<<(n + 7) / 8, 256>>>(att2, out, 0, n);
}